// round 8
// baseline (speedup 1.0000x reference)
#include <cuda_runtime.h>
#include <cstdint>

// CategoryAdder: out[b,s,:] = inputs[b,s,:] + emb
//   emb = table[categories[b,s]]  if categories[b,s] != 0 AND s != mask_positions[b]
// B=64, S=2048, D=512. categories/mask_positions int32 on device.
//
// R8: 256-bit (v8.f32) loads/stores — sm_100 native. 4 x 32B per thread,
// block-strided, fully front-batched. Unconditional table gather (masked rows
// are ~0.05%), predicated add. Streaming cache ops on the 512MB in/out stream.

static constexpr int D8 = 64;                                    // float8 per row
static constexpr long long NVEC8 = (long long)64 * 2048 * D8;    // 8,388,608
static constexpr int THREADS = 256;
static constexpr int VPT = 4;                                    // float8 per thread
static constexpr int BLK_VEC = THREADS * VPT;                    // 1024 float8 / block

__device__ __forceinline__ void ldg256_cs(const float* p, float* v) {
    asm volatile("ld.global.cs.v8.f32 {%0,%1,%2,%3,%4,%5,%6,%7}, [%8];"
        : "=f"(v[0]), "=f"(v[1]), "=f"(v[2]), "=f"(v[3]),
          "=f"(v[4]), "=f"(v[5]), "=f"(v[6]), "=f"(v[7])
        : "l"(p));
}

__device__ __forceinline__ void ldg256_nc(const float* p, float* v) {
    asm volatile("ld.global.nc.v8.f32 {%0,%1,%2,%3,%4,%5,%6,%7}, [%8];"
        : "=f"(v[0]), "=f"(v[1]), "=f"(v[2]), "=f"(v[3]),
          "=f"(v[4]), "=f"(v[5]), "=f"(v[6]), "=f"(v[7])
        : "l"(p));
}

__device__ __forceinline__ void stg256_cs(float* p, const float* v) {
    asm volatile("st.global.cs.v8.f32 [%0], {%1,%2,%3,%4,%5,%6,%7,%8};"
        :: "l"(p),
           "f"(v[0]), "f"(v[1]), "f"(v[2]), "f"(v[3]),
           "f"(v[4]), "f"(v[5]), "f"(v[6]), "f"(v[7])
        : "memory");
}

__global__ __launch_bounds__(THREADS)
void category_adder_kernel(const float* __restrict__ in,
                           const int* __restrict__ cat,
                           const int* __restrict__ mask_pos,
                           const float* __restrict__ table,
                           float* __restrict__ out)
{
    const long long base = (long long)blockIdx.x * BLK_VEC + threadIdx.x;

    long long idx[VPT];
    const float* tp[VPT];
    float mul[VPT];                 // 1.0 if add, 0.0 if masked
    float v[VPT][8];
    float e[VPT][8];

    // Front-batch index math + scalar category/mask loads (L1-hit broadcasts)
    #pragma unroll
    for (int k = 0; k < VPT; k++) {
        idx[k] = base + (long long)k * THREADS;   // float8 index
        long long row = idx[k] >> 6;              // / D8
        int col8 = (int)(idx[k] & 63);
        int b = (int)(row >> 11);                 // / S
        int s = (int)(row & 2047);                // % S
        int c  = __ldg(&cat[row]);
        int mp = __ldg(&mask_pos[b]);
        mul[k] = (c != 0 && s != mp) ? 1.0f : 0.0f;
        tp[k]  = table + ((long long)c << 9) + (col8 << 3);
    }

    // Front-batch 4 streaming 256-bit input loads
    #pragma unroll
    for (int k = 0; k < VPT; k++)
        ldg256_cs(in + (idx[k] << 3), v[k]);

    // Front-batch 4 table gathers (L2-resident), unconditional
    #pragma unroll
    for (int k = 0; k < VPT; k++)
        ldg256_nc(tp[k], e[k]);

    // Predicated add (fma with 0/1 multiplier -> branch-free)
    #pragma unroll
    for (int k = 0; k < VPT; k++) {
        #pragma unroll
        for (int i = 0; i < 8; i++)
            v[k][i] = fmaf(e[k][i], mul[k], v[k][i]);
    }

    // Streaming 256-bit stores
    #pragma unroll
    for (int k = 0; k < VPT; k++)
        stg256_cs(out + (idx[k] << 3), v[k]);
}

extern "C" void kernel_launch(void* const* d_in, const int* in_sizes, int n_in,
                              void* d_out, int out_size)
{
    const float* inputs  = (const float*)d_in[0];
    const int*   cats    = (const int*)d_in[1];
    const int*   maskpos = (const int*)d_in[2];
    const float* table   = (const float*)d_in[3];
    float*       out     = (float*)d_out;

    const unsigned nblk = (unsigned)(NVEC8 / BLK_VEC);   // 8192, exact
    category_adder_kernel<<<nblk, THREADS>>>(inputs, cats, maskpos, table, out);
}

// round 9
// speedup vs baseline: 1.0594x; 1.0594x over previous
#include <cuda_runtime.h>
#include <cstdint>

// CategoryAdder: out[b,s,:] = inputs[b,s,:] + emb
//   emb = table[categories[b,s]]  if categories[b,s] != 0 AND s != mask_positions[b]
//         0                       otherwise
// B=64, S=2048, D=512. categories/mask_positions int32 on device.
//
// R9: converged-design refinement of R4 (best: 84.0us, 6.28TB/s).
// THREADS=512, VPT=4 -> each CTA streams a contiguous 32KB span (4 rows),
// fully front-batched loads, streaming cache ops protect the L2-resident table.
// Evidence: 4 designs all pin at ~6.3TB/s => DRAM-ceiling-bound; this tweak
// targets HBM burst locality only.

static constexpr int D4 = 128;                                   // float4 per row
static constexpr long long NVEC = (long long)64 * 2048 * D4;     // 16,777,216
static constexpr int THREADS = 512;
static constexpr int VPT = 4;                                    // float4 per thread
static constexpr int BLK_VEC = THREADS * VPT;                    // 2048 float4 / block

__global__ __launch_bounds__(THREADS)
void category_adder_kernel(const float4* __restrict__ in,
                           const int* __restrict__ cat,
                           const int* __restrict__ mask_pos,
                           const float4* __restrict__ table,
                           float4* __restrict__ out)
{
    const long long base = (long long)blockIdx.x * BLK_VEC + threadIdx.x;

    long long idx[VPT];
    long long trow[VPT];
    bool add[VPT];
    float4 v[VPT];

    // Front-batch index math + scalar category/mask loads (L1-hit broadcasts)
    #pragma unroll
    for (int k = 0; k < VPT; k++) {
        idx[k] = base + (long long)k * THREADS;
        long long row = idx[k] >> 7;          // / D4
        int col = (int)(idx[k] & 127);
        int b  = (int)(row >> 11);            // / S
        int s  = (int)(row & 2047);           // % S
        int c  = __ldg(&cat[row]);
        int mp = __ldg(&mask_pos[b]);
        add[k] = (c != 0) && (s != mp);
        trow[k] = (long long)c * D4 + col;
    }

    // Front-batch 4 streaming input loads (evict-first: read-once data)
    #pragma unroll
    for (int k = 0; k < VPT; k++)
        v[k] = __ldcs(&in[idx[k]]);

    // Table gathers (L2-resident) + add
    #pragma unroll
    for (int k = 0; k < VPT; k++) {
        if (add[k]) {
            float4 e = __ldg(&table[trow[k]]);
            v[k].x += e.x; v[k].y += e.y; v[k].z += e.z; v[k].w += e.w;
        }
    }

    // Streaming stores (write-once)
    #pragma unroll
    for (int k = 0; k < VPT; k++)
        __stcs(&out[idx[k]], v[k]);
}

extern "C" void kernel_launch(void* const* d_in, const int* in_sizes, int n_in,
                              void* d_out, int out_size)
{
    const float4* inputs  = (const float4*)d_in[0];
    const int*    cats    = (const int*)d_in[1];
    const int*    maskpos = (const int*)d_in[2];
    const float4* table   = (const float4*)d_in[3];
    float4*       out     = (float4*)d_out;

    const unsigned nblk = (unsigned)(NVEC / BLK_VEC);   // 8192, exact
    category_adder_kernel<<<nblk, THREADS>>>(inputs, cats, maskpos, table, out);
}